// round 1
// baseline (speedup 1.0000x reference)
#include <cuda_runtime.h>
#include <math.h>

#define NN 100000
#define NE 1600000
#define DF 128
#define NG 512
#define DH 256

// ------------------- scratch (__device__ globals; no allocation) -------------------
static __device__ int   g_cnt[NN];
static __device__ int   g_wptr[NN];
static __device__ int   g_rowptr[NN + 1];
static __device__ int   g_col[NE];
static __device__ float g_dinv[NN];
static __device__ __align__(16) float g_x0[(size_t)NN * DF];
static __device__ __align__(16) float g_x1[(size_t)NN * DF];
static __device__ __align__(16) float g_h [(size_t)NN * DF];
static __device__ __align__(16) float g_Wmod[DF * DF];
static __device__ __align__(16) float g_dvec[DF];
static __device__ float g_bnsum[DF];
static __device__ float g_bnsq[DF];
static __device__ float g_affa[DF];
static __device__ float g_affc[DF];
static __device__ __align__(16) float g_pool[NG * DF];
static __device__ float g_gcnt[NG];
static __device__ float g_h0[NG * DH];
static __device__ float g_h1[NG * DH];
static __device__ float g_s0[DH];
static __device__ float g_q0[DH];
static __device__ float g_ha[DH];
static __device__ float g_hc[DH];

// ------------------- utility -------------------
__global__ void k_zero_f(float* p, int n) {
    int i = blockIdx.x * blockDim.x + threadIdx.x;
    if (i < n) p[i] = 0.f;
}
__global__ void k_zero_i(int* p, int n) {
    int i = blockIdx.x * blockDim.x + threadIdx.x;
    if (i < n) p[i] = 0;
}

// ------------------- CSR build -------------------
__global__ void k_hist(const int* __restrict__ dst) {
    int e = blockIdx.x * blockDim.x + threadIdx.x;
    if (e < NE) atomicAdd(&g_cnt[dst[e]], 1);
}

__global__ void k_dinv() {
    int v = blockIdx.x * blockDim.x + threadIdx.x;
    if (v < NN) g_dinv[v] = rsqrtf((float)g_cnt[v] + 1.0f);
}

// single-block exclusive scan of g_cnt -> g_rowptr (and g_wptr copy)
__global__ void k_scan() {
    __shared__ int ssum[1024];
    const int CH = (NN + 1023) / 1024;  // 98
    int t = threadIdx.x;
    int beg = t * CH;
    int end = beg + CH; if (end > NN) end = NN;
    int s = 0;
    for (int i = beg; i < end && i < NN; i++) s += g_cnt[i];
    ssum[t] = s;
    __syncthreads();
    for (int off = 1; off < 1024; off <<= 1) {
        int v = (t >= off) ? ssum[t - off] : 0;
        __syncthreads();
        ssum[t] += v;
        __syncthreads();
    }
    int run = (t > 0) ? ssum[t - 1] : 0;  // exclusive prefix
    for (int i = beg; i < end && i < NN; i++) {
        g_rowptr[i] = run;
        g_wptr[i]   = run;
        run += g_cnt[i];
    }
    if (beg < NN && end == NN) g_rowptr[NN] = run;
}

__global__ void k_fill(const int* __restrict__ src, const int* __restrict__ dst) {
    int e = blockIdx.x * blockDim.x + threadIdx.x;
    if (e < NE) {
        int v = dst[e];
        int pos = atomicAdd(&g_wptr[v], 1);
        g_col[pos] = src[e];
    }
}

// ------------------- SGEMM: C[M,128] = A[M,128] @ B[128,128] (+ dvec row) -------------------
// BM=128, BN=128, BK=8, TM=8, TN=8, 256 threads
__global__ void __launch_bounds__(256) k_sgemm(
    const float* __restrict__ A, const float* __restrict__ B,
    const float* __restrict__ dvec, float* __restrict__ C, int M)
{
    const int BM = 128, BN = 128, BK = 8, TM = 8, TN = 8;
    __shared__ __align__(16) float As[BK * BM];  // transposed: As[k][m]
    __shared__ __align__(16) float Bs[BK * BN];

    int tid  = threadIdx.x;
    int row0 = blockIdx.x * BM;
    int tr = tid / 16;            // 0..15
    int tc = tid % 16;            // 0..15

    float acc[TM][TN];
#pragma unroll
    for (int i = 0; i < TM; i++)
#pragma unroll
        for (int j = 0; j < TN; j++) acc[i][j] = 0.f;

    int arow = tid >> 1;           // 0..127
    int acol = (tid & 1) * 4;      // 0 or 4
    int brow = tid >> 5;           // 0..7
    int bcol = (tid & 31) * 4;     // 0..124

    for (int kk = 0; kk < 128; kk += BK) {
        float4 av;
        if (row0 + arow < M)
            av = *(const float4*)(A + (size_t)(row0 + arow) * 128 + kk + acol);
        else
            av = make_float4(0.f, 0.f, 0.f, 0.f);
        As[(acol + 0) * BM + arow] = av.x;
        As[(acol + 1) * BM + arow] = av.y;
        As[(acol + 2) * BM + arow] = av.z;
        As[(acol + 3) * BM + arow] = av.w;

        float4 bv = *(const float4*)(B + (size_t)(kk + brow) * 128 + bcol);
        *(float4*)(Bs + brow * BN + bcol) = bv;
        __syncthreads();

#pragma unroll
        for (int k = 0; k < BK; k++) {
            float ra[TM], rb[TN];
            float4 ra0 = *(const float4*)(As + k * BM + tr * TM);
            float4 ra1 = *(const float4*)(As + k * BM + tr * TM + 4);
            ra[0] = ra0.x; ra[1] = ra0.y; ra[2] = ra0.z; ra[3] = ra0.w;
            ra[4] = ra1.x; ra[5] = ra1.y; ra[6] = ra1.z; ra[7] = ra1.w;
            float4 rb0 = *(const float4*)(Bs + k * BN + tc * TN);
            float4 rb1 = *(const float4*)(Bs + k * BN + tc * TN + 4);
            rb[0] = rb0.x; rb[1] = rb0.y; rb[2] = rb0.z; rb[3] = rb0.w;
            rb[4] = rb1.x; rb[5] = rb1.y; rb[6] = rb1.z; rb[7] = rb1.w;
#pragma unroll
            for (int i = 0; i < TM; i++)
#pragma unroll
                for (int j = 0; j < TN; j++)
                    acc[i][j] = fmaf(ra[i], rb[j], acc[i][j]);
        }
        __syncthreads();
    }

    float dv[TN];
#pragma unroll
    for (int j = 0; j < TN; j++) dv[j] = dvec ? dvec[tc * TN + j] : 0.f;

#pragma unroll
    for (int i = 0; i < TM; i++) {
        int r = row0 + tr * TM + i;
        if (r < M) {
            float4 o0 = make_float4(acc[i][0] + dv[0], acc[i][1] + dv[1],
                                    acc[i][2] + dv[2], acc[i][3] + dv[3]);
            float4 o1 = make_float4(acc[i][4] + dv[4], acc[i][5] + dv[5],
                                    acc[i][6] + dv[6], acc[i][7] + dv[7]);
            *(float4*)(C + (size_t)r * 128 + tc * TN)     = o0;
            *(float4*)(C + (size_t)r * 128 + tc * TN + 4) = o1;
        }
    }
}

// ------------------- GCN aggregation + bias + relu + fused BN stats -------------------
// one warp per node; lane owns 4 features
__global__ void __launch_bounds__(256) k_agg(
    const float* __restrict__ h, const float* __restrict__ bias,
    float* __restrict__ xout)
{
    __shared__ float bs[DF], bq[DF];
    int tid = threadIdx.x;
    if (tid < DF) { bs[tid] = 0.f; bq[tid] = 0.f; }
    __syncthreads();

    int lane = tid & 31;
    int w    = tid >> 5;
    int warpId = blockIdx.x * (blockDim.x >> 5) + w;
    int nW     = gridDim.x * (blockDim.x >> 5);

    float4 bv = *(const float4*)(bias + lane * 4);
    float ls0 = 0, ls1 = 0, ls2 = 0, ls3 = 0;
    float lq0 = 0, lq1 = 0, lq2 = 0, lq3 = 0;

    for (int v = warpId; v < NN; v += nW) {
        float dv = g_dinv[v];
        float4 hv = *((const float4*)(h + (size_t)v * DF) + lane);  // self loop
        float ax = hv.x * dv, ay = hv.y * dv, az = hv.z * dv, aw = hv.w * dv;

        int beg = g_rowptr[v], end = g_rowptr[v + 1];
        for (int e0 = beg; e0 < end; e0 += 32) {
            int idx = e0 + lane;
            int   sl = (idx < end) ? g_col[idx]  : 0;
            float dl = (idx < end) ? g_dinv[sl]  : 0.f;
            int m = end - e0; if (m > 32) m = 32;
            for (int j = 0; j < m; j++) {
                int   sj  = __shfl_sync(0xffffffffu, sl, j);
                float dsj = __shfl_sync(0xffffffffu, dl, j);
                float4 hs = *((const float4*)(h + (size_t)sj * DF) + lane);
                ax = fmaf(hs.x, dsj, ax);
                ay = fmaf(hs.y, dsj, ay);
                az = fmaf(hs.z, dsj, az);
                aw = fmaf(hs.w, dsj, aw);
            }
        }
        float ox = fmaxf(fmaf(ax, dv, bv.x), 0.f);
        float oy = fmaxf(fmaf(ay, dv, bv.y), 0.f);
        float oz = fmaxf(fmaf(az, dv, bv.z), 0.f);
        float ow = fmaxf(fmaf(aw, dv, bv.w), 0.f);
        *((float4*)(xout + (size_t)v * DF) + lane) = make_float4(ox, oy, oz, ow);
        ls0 += ox; lq0 += ox * ox;
        ls1 += oy; lq1 += oy * oy;
        ls2 += oz; lq2 += oz * oz;
        ls3 += ow; lq3 += ow * ow;
    }
    atomicAdd(&bs[lane * 4 + 0], ls0); atomicAdd(&bq[lane * 4 + 0], lq0);
    atomicAdd(&bs[lane * 4 + 1], ls1); atomicAdd(&bq[lane * 4 + 1], lq1);
    atomicAdd(&bs[lane * 4 + 2], ls2); atomicAdd(&bq[lane * 4 + 2], lq2);
    atomicAdd(&bs[lane * 4 + 3], ls3); atomicAdd(&bq[lane * 4 + 3], lq3);
    __syncthreads();
    if (tid < DF) {
        atomicAdd(&g_bnsum[tid], bs[tid]);
        atomicAdd(&g_bnsq[tid],  bq[tid]);
    }
}

// ------------------- BN affine parameters: a = g*rsqrt(var+eps), c = beta - a*mean -------------------
__global__ void k_bnaff(const float* __restrict__ sum, const float* __restrict__ sq,
                        const float* __restrict__ gamma, const float* __restrict__ beta,
                        float* __restrict__ a, float* __restrict__ c,
                        int D, float invN)
{
    int j = blockIdx.x * blockDim.x + threadIdx.x;
    if (j >= D) return;
    float m   = sum[j] * invN;
    float var = sq[j] * invN - m * m;
    float aj  = gamma[j] * rsqrtf(var + 1e-5f);
    a[j] = aj;
    c[j] = beta[j] - aj * m;
}

// Wmod[k][j] = a[k] * W[k][j]
__global__ void k_wprep(const float* __restrict__ W) {
    int i = blockIdx.x * blockDim.x + threadIdx.x;
    if (i < DF * DF) g_Wmod[i] = g_affa[i >> 7] * W[i];
}
// d[j] = sum_k c[k] * W[k][j]
__global__ void k_dvec(const float* __restrict__ W) {
    int j = threadIdx.x;
    if (j < DF) {
        float s = 0.f;
        for (int k = 0; k < DF; k++) s = fmaf(g_affc[k], W[k * DF + j], s);
        g_dvec[j] = s;
    }
}

// ------------------- global_add_pool (batch is sorted -> run-length accumulation) -------------------
__global__ void k_pool(const float* __restrict__ x, const int* __restrict__ batch) {
    int lane = threadIdx.x & 31;
    int w    = (blockIdx.x * blockDim.x + threadIdx.x) >> 5;
    int nW   = (gridDim.x * blockDim.x) >> 5;
    int C    = (NN + nW - 1) / nW;
    int beg = w * C;
    int end = beg + C; if (end > NN) end = NN;
    if (beg >= end) return;

    float a0 = 0, a1 = 0, a2 = 0, a3 = 0, cntf = 0;
    int cur = batch[beg];
    for (int v = beg; v < end; v++) {
        int g = batch[v];
        if (g != cur) {
            atomicAdd(&g_pool[cur * DF + lane * 4 + 0], a0);
            atomicAdd(&g_pool[cur * DF + lane * 4 + 1], a1);
            atomicAdd(&g_pool[cur * DF + lane * 4 + 2], a2);
            atomicAdd(&g_pool[cur * DF + lane * 4 + 3], a3);
            if (lane == 0) atomicAdd(&g_gcnt[cur], cntf);
            a0 = a1 = a2 = a3 = 0.f; cntf = 0.f; cur = g;
        }
        float4 xv = *((const float4*)(x + (size_t)v * DF) + lane);
        a0 += xv.x; a1 += xv.y; a2 += xv.z; a3 += xv.w; cntf += 1.f;
    }
    atomicAdd(&g_pool[cur * DF + lane * 4 + 0], a0);
    atomicAdd(&g_pool[cur * DF + lane * 4 + 1], a1);
    atomicAdd(&g_pool[cur * DF + lane * 4 + 2], a2);
    atomicAdd(&g_pool[cur * DF + lane * 4 + 3], a3);
    if (lane == 0) atomicAdd(&g_gcnt[cur], cntf);
}

// ------------------- head -------------------
// h0 = relu((a2*pool + c2*cnt) @ Wh0 + bh0), fused BN stats
__global__ void __launch_bounds__(256) k_hg0(const float* __restrict__ Wh0,
                                             const float* __restrict__ bh0) {
    __shared__ float sx[DF];
    int g = blockIdx.x, j = threadIdx.x;
    if (j < DF) sx[j] = g_affa[j] * g_pool[g * DF + j] + g_affc[j] * g_gcnt[g];
    __syncthreads();
    float acc = bh0[j];
#pragma unroll 8
    for (int k = 0; k < DF; k++) acc = fmaf(sx[k], Wh0[k * DH + j], acc);
    float v = fmaxf(acc, 0.f);
    g_h0[g * DH + j] = v;
    atomicAdd(&g_s0[j], v);
    atomicAdd(&g_q0[j], v * v);
}

// h1 = relu((a*h0 + c) @ Wh1 + bh1), fused BN stats
__global__ void __launch_bounds__(256) k_hg1(const float* __restrict__ Wh1,
                                             const float* __restrict__ bh1) {
    __shared__ float sx[DH];
    int g = blockIdx.x, j = threadIdx.x;
    sx[j] = g_ha[j] * g_h0[g * DH + j] + g_hc[j];
    __syncthreads();
    float acc = bh1[j];
#pragma unroll 8
    for (int k = 0; k < DH; k++) acc = fmaf(sx[k], Wh1[k * DH + j], acc);
    float v = fmaxf(acc, 0.f);
    g_h1[g * DH + j] = v;
    atomicAdd(&g_s0[j], v);
    atomicAdd(&g_q0[j], v * v);
}

// out[g] = (a*h1 + c) @ Wout + bout
__global__ void __launch_bounds__(256) k_final(const float* __restrict__ Wout,
                                               const float* __restrict__ bout,
                                               float* __restrict__ out) {
    __shared__ float red[DH];
    int g = blockIdx.x, t = threadIdx.x;
    red[t] = (g_ha[t] * g_h1[g * DH + t] + g_hc[t]) * Wout[t];
    __syncthreads();
    for (int o = DH / 2; o > 0; o >>= 1) {
        if (t < o) red[t] += red[t + o];
        __syncthreads();
    }
    if (t == 0) out[g] = red[0] + bout[0];
}

// ------------------- launch -------------------
extern "C" void kernel_launch(void* const* d_in, const int* in_sizes, int n_in,
                              void* d_out, int out_size) {
    const float* x   = (const float*)d_in[0];
    const int*   ei  = (const int*)d_in[1];
    const int*   bat = (const int*)d_in[2];
    const float* Wc  = (const float*)d_in[3];
    const float* bc  = (const float*)d_in[4];
    const float* gc  = (const float*)d_in[5];
    const float* bec = (const float*)d_in[6];
    const float* Wh0 = (const float*)d_in[7];
    const float* bh0 = (const float*)d_in[8];
    const float* gh0 = (const float*)d_in[9];
    const float* beh0= (const float*)d_in[10];
    const float* Wh1 = (const float*)d_in[11];
    const float* bh1 = (const float*)d_in[12];
    const float* gh1 = (const float*)d_in[13];
    const float* beh1= (const float*)d_in[14];
    const float* Wout= (const float*)d_in[15];
    const float* bout= (const float*)d_in[16];
    float* out = (float*)d_out;

    const int* src = ei;
    const int* dst = ei + NE;

    float *p_x0, *p_x1, *p_h, *p_Wmod, *p_dvec, *p_bnsum, *p_bnsq;
    float *p_affa, *p_affc, *p_pool, *p_gcnt, *p_s0, *p_q0, *p_ha, *p_hc;
    int   *p_cnt;
    cudaGetSymbolAddress((void**)&p_x0,   g_x0);
    cudaGetSymbolAddress((void**)&p_x1,   g_x1);
    cudaGetSymbolAddress((void**)&p_h,    g_h);
    cudaGetSymbolAddress((void**)&p_Wmod, g_Wmod);
    cudaGetSymbolAddress((void**)&p_dvec, g_dvec);
    cudaGetSymbolAddress((void**)&p_bnsum,g_bnsum);
    cudaGetSymbolAddress((void**)&p_bnsq, g_bnsq);
    cudaGetSymbolAddress((void**)&p_affa, g_affa);
    cudaGetSymbolAddress((void**)&p_affc, g_affc);
    cudaGetSymbolAddress((void**)&p_pool, g_pool);
    cudaGetSymbolAddress((void**)&p_gcnt, g_gcnt);
    cudaGetSymbolAddress((void**)&p_s0,   g_s0);
    cudaGetSymbolAddress((void**)&p_q0,   g_q0);
    cudaGetSymbolAddress((void**)&p_ha,   g_ha);
    cudaGetSymbolAddress((void**)&p_hc,   g_hc);
    cudaGetSymbolAddress((void**)&p_cnt,  g_cnt);

    const int T = 256;
    const int gemmBlocks = (NN + 127) / 128;

    // ---- CSR build + degree ----
    k_zero_i<<<(NN + T - 1) / T, T>>>(p_cnt, NN);
    k_hist<<<(NE + T - 1) / T, T>>>(dst);
    k_dinv<<<(NN + T - 1) / T, T>>>();
    k_scan<<<1, 1024>>>();
    k_fill<<<(NE + T - 1) / T, T>>>(src, dst);

    // ---- conv layer 0 ----
    k_sgemm<<<gemmBlocks, T>>>(x, Wc, nullptr, p_h, NN);
    k_zero_f<<<1, DF>>>(p_bnsum, DF);
    k_zero_f<<<1, DF>>>(p_bnsq, DF);
    k_agg<<<2048, T>>>(p_h, bc, p_x0);
    k_bnaff<<<1, DF>>>(p_bnsum, p_bnsq, gc, bec, p_affa, p_affc, DF, 1.0f / NN);

    // ---- conv layer 1 (BN0 folded into GEMM) ----
    k_wprep<<<(DF * DF + T - 1) / T, T>>>(Wc + DF * DF);
    k_dvec<<<1, DF>>>(Wc + DF * DF);
    k_sgemm<<<gemmBlocks, T>>>(p_x0, p_Wmod, p_dvec, p_h, NN);
    k_zero_f<<<1, DF>>>(p_bnsum, DF);
    k_zero_f<<<1, DF>>>(p_bnsq, DF);
    k_agg<<<2048, T>>>(p_h, bc + DF, p_x1);
    k_bnaff<<<1, DF>>>(p_bnsum, p_bnsq, gc + DF, bec + DF, p_affa, p_affc, DF, 1.0f / NN);

    // ---- conv layer 2 ----
    k_wprep<<<(DF * DF + T - 1) / T, T>>>(Wc + 2 * DF * DF);
    k_dvec<<<1, DF>>>(Wc + 2 * DF * DF);
    k_sgemm<<<gemmBlocks, T>>>(p_x1, p_Wmod, p_dvec, p_h, NN);
    k_zero_f<<<1, DF>>>(p_bnsum, DF);
    k_zero_f<<<1, DF>>>(p_bnsq, DF);
    k_agg<<<2048, T>>>(p_h, bc + 2 * DF, p_x0);
    k_bnaff<<<1, DF>>>(p_bnsum, p_bnsq, gc + 2 * DF, bec + 2 * DF, p_affa, p_affc, DF, 1.0f / NN);

    // ---- pool (BN2 applied in head gemm0 via g_affa/g_affc) ----
    k_zero_f<<<(NG * DF + T - 1) / T, T>>>(p_pool, NG * DF);
    k_zero_f<<<(NG + T - 1) / T, T>>>(p_gcnt, NG);
    k_pool<<<128, T>>>(p_x0, bat);

    // ---- head ----
    k_zero_f<<<1, DH>>>(p_s0, DH);
    k_zero_f<<<1, DH>>>(p_q0, DH);
    k_hg0<<<NG, DH>>>(Wh0, bh0);
    k_bnaff<<<1, DH>>>(p_s0, p_q0, gh0, beh0, p_ha, p_hc, DH, 1.0f / NG);
    k_zero_f<<<1, DH>>>(p_s0, DH);
    k_zero_f<<<1, DH>>>(p_q0, DH);
    k_hg1<<<NG, DH>>>(Wh1, bh1);
    k_bnaff<<<1, DH>>>(p_s0, p_q0, gh1, beh1, p_ha, p_hc, DH, 1.0f / NG);
    k_final<<<NG, DH>>>(Wout, bout, out);
}

// round 2
// speedup vs baseline: 1.2292x; 1.2292x over previous
#include <cuda_runtime.h>
#include <math.h>

#define NN 100000
#define NE 1600000
#define DF 128
#define NG 512
#define DH 256
#define SB ((NN + 255) / 256)   // 391 scan blocks

// ------------------- scratch (__device__ globals; no allocation) -------------------
static __device__ int   g_cnt[NN];
static __device__ int   g_wptr[NN];
static __device__ int   g_rowptr[NN + 1];
static __device__ int   g_bsum[512];
static __device__ int   g_boff[512];
static __device__ int   g_col[NE];
static __device__ float g_dinv[NN];
static __device__ __align__(16) float g_x0[(size_t)NN * DF];
static __device__ __align__(16) float g_x1[(size_t)NN * DF];
static __device__ __align__(16) float g_h [(size_t)NN * DF];
static __device__ __align__(16) float g_Wmod[DF * DF];
static __device__ __align__(16) float g_dvec[DF];
static __device__ float g_bnsum[DF];
static __device__ float g_bnsq[DF];
static __device__ float g_affa[DF];
static __device__ float g_affc[DF];
static __device__ __align__(16) float g_pool[NG * DF];
static __device__ float g_gcnt[NG];
static __device__ float g_h0[NG * DH];
static __device__ float g_h1[NG * DH];
static __device__ float g_s0[DH];
static __device__ float g_q0[DH];
static __device__ float g_ha[DH];
static __device__ float g_hc[DH];

// ------------------- utility -------------------
__global__ void k_zero_f(float* p, int n) {
    int i = blockIdx.x * blockDim.x + threadIdx.x;
    if (i < n) p[i] = 0.f;
}
__global__ void k_zero_i(int* p, int n) {
    int i = blockIdx.x * blockDim.x + threadIdx.x;
    if (i < n) p[i] = 0;
}

// ------------------- CSR build -------------------
__global__ void k_hist(const int* __restrict__ dst) {
    int e = blockIdx.x * blockDim.x + threadIdx.x;
    if (e < NE) atomicAdd(&g_cnt[dst[e]], 1);
}

__global__ void k_dinv() {
    int v = blockIdx.x * blockDim.x + threadIdx.x;
    if (v < NN) g_dinv[v] = rsqrtf((float)g_cnt[v] + 1.0f);
}

// --- 3-phase full-chip exclusive scan of g_cnt -> g_rowptr / g_wptr ---
__global__ void __launch_bounds__(256) k_scanA() {
    __shared__ int s[256];
    int t = threadIdx.x;
    int i = blockIdx.x * 256 + t;
    int v = (i < NN) ? g_cnt[i] : 0;
    s[t] = v;
    __syncthreads();
#pragma unroll
    for (int off = 1; off < 256; off <<= 1) {
        int u = (t >= off) ? s[t - off] : 0;
        __syncthreads();
        s[t] += u;
        __syncthreads();
    }
    if (i < NN) g_rowptr[i] = s[t] - v;          // local exclusive prefix
    if (t == 255) g_bsum[blockIdx.x] = s[255];   // block total
}

__global__ void __launch_bounds__(512) k_scanB() {
    __shared__ int s[512];
    int t = threadIdx.x;
    int v = (t < SB) ? g_bsum[t] : 0;
    s[t] = v;
    __syncthreads();
#pragma unroll
    for (int off = 1; off < 512; off <<= 1) {
        int u = (t >= off) ? s[t - off] : 0;
        __syncthreads();
        s[t] += u;
        __syncthreads();
    }
    g_boff[t] = s[t] - v;                        // exclusive block offsets
    if (t == 0) g_rowptr[NN] = NE;               // total edges is static
}

__global__ void __launch_bounds__(256) k_scanC() {
    int i = blockIdx.x * 256 + threadIdx.x;
    if (i < NN) {
        int r = g_rowptr[i] + g_boff[blockIdx.x];
        g_rowptr[i] = r;
        g_wptr[i]   = r;
    }
}

__global__ void k_fill(const int* __restrict__ src, const int* __restrict__ dst) {
    int e = blockIdx.x * blockDim.x + threadIdx.x;
    if (e < NE) {
        int v = dst[e];
        int pos = atomicAdd(&g_wptr[v], 1);
        g_col[pos] = src[e];
    }
}

// ------------------- SGEMM: C[M,128] = A[M,128] @ B[128,128] (+ dvec row) -------------------
// BM=128, BN=128, BK=8, TM=8, TN=8, 256 threads
__global__ void __launch_bounds__(256) k_sgemm(
    const float* __restrict__ A, const float* __restrict__ B,
    const float* __restrict__ dvec, float* __restrict__ C, int M)
{
    const int BM = 128, BN = 128, BK = 8, TM = 8, TN = 8;
    __shared__ __align__(16) float As[BK * BM];  // transposed: As[k][m]
    __shared__ __align__(16) float Bs[BK * BN];

    int tid  = threadIdx.x;
    int row0 = blockIdx.x * BM;
    int tr = tid / 16;            // 0..15
    int tc = tid % 16;            // 0..15

    float acc[TM][TN];
#pragma unroll
    for (int i = 0; i < TM; i++)
#pragma unroll
        for (int j = 0; j < TN; j++) acc[i][j] = 0.f;

    int arow = tid >> 1;           // 0..127
    int acol = (tid & 1) * 4;      // 0 or 4
    int brow = tid >> 5;           // 0..7
    int bcol = (tid & 31) * 4;     // 0..124

    for (int kk = 0; kk < 128; kk += BK) {
        float4 av;
        if (row0 + arow < M)
            av = *(const float4*)(A + (size_t)(row0 + arow) * 128 + kk + acol);
        else
            av = make_float4(0.f, 0.f, 0.f, 0.f);
        As[(acol + 0) * BM + arow] = av.x;
        As[(acol + 1) * BM + arow] = av.y;
        As[(acol + 2) * BM + arow] = av.z;
        As[(acol + 3) * BM + arow] = av.w;

        float4 bv = *(const float4*)(B + (size_t)(kk + brow) * 128 + bcol);
        *(float4*)(Bs + brow * BN + bcol) = bv;
        __syncthreads();

#pragma unroll
        for (int k = 0; k < BK; k++) {
            float ra[TM], rb[TN];
            float4 ra0 = *(const float4*)(As + k * BM + tr * TM);
            float4 ra1 = *(const float4*)(As + k * BM + tr * TM + 4);
            ra[0] = ra0.x; ra[1] = ra0.y; ra[2] = ra0.z; ra[3] = ra0.w;
            ra[4] = ra1.x; ra[5] = ra1.y; ra[6] = ra1.z; ra[7] = ra1.w;
            float4 rb0 = *(const float4*)(Bs + k * BN + tc * TN);
            float4 rb1 = *(const float4*)(Bs + k * BN + tc * TN + 4);
            rb[0] = rb0.x; rb[1] = rb0.y; rb[2] = rb0.z; rb[3] = rb0.w;
            rb[4] = rb1.x; rb[5] = rb1.y; rb[6] = rb1.z; rb[7] = rb1.w;
#pragma unroll
            for (int i = 0; i < TM; i++)
#pragma unroll
                for (int j = 0; j < TN; j++)
                    acc[i][j] = fmaf(ra[i], rb[j], acc[i][j]);
        }
        __syncthreads();
    }

    float dv[TN];
#pragma unroll
    for (int j = 0; j < TN; j++) dv[j] = dvec ? dvec[tc * TN + j] : 0.f;

#pragma unroll
    for (int i = 0; i < TM; i++) {
        int r = row0 + tr * TM + i;
        if (r < M) {
            float4 o0 = make_float4(acc[i][0] + dv[0], acc[i][1] + dv[1],
                                    acc[i][2] + dv[2], acc[i][3] + dv[3]);
            float4 o1 = make_float4(acc[i][4] + dv[4], acc[i][5] + dv[5],
                                    acc[i][6] + dv[6], acc[i][7] + dv[7]);
            *(float4*)(C + (size_t)r * 128 + tc * TN)     = o0;
            *(float4*)(C + (size_t)r * 128 + tc * TN + 4) = o1;
        }
    }
}

// ------------------- GCN aggregation + bias + relu + fused BN stats -------------------
// one warp per node; lane owns 4 features
__global__ void __launch_bounds__(256) k_agg(
    const float* __restrict__ h, const float* __restrict__ bias,
    float* __restrict__ xout)
{
    __shared__ float bs[DF], bq[DF];
    int tid = threadIdx.x;
    if (tid < DF) { bs[tid] = 0.f; bq[tid] = 0.f; }
    __syncthreads();

    int lane = tid & 31;
    int w    = tid >> 5;
    int warpId = blockIdx.x * (blockDim.x >> 5) + w;
    int nW     = gridDim.x * (blockDim.x >> 5);

    float4 bv = *(const float4*)(bias + lane * 4);
    float ls0 = 0, ls1 = 0, ls2 = 0, ls3 = 0;
    float lq0 = 0, lq1 = 0, lq2 = 0, lq3 = 0;

    for (int v = warpId; v < NN; v += nW) {
        float dv = g_dinv[v];
        float4 hv = *((const float4*)(h + (size_t)v * DF) + lane);  // self loop
        float ax = hv.x * dv, ay = hv.y * dv, az = hv.z * dv, aw = hv.w * dv;

        int beg = g_rowptr[v], end = g_rowptr[v + 1];
        for (int e0 = beg; e0 < end; e0 += 32) {
            int idx = e0 + lane;
            int   sl = (idx < end) ? g_col[idx]  : 0;
            float dl = (idx < end) ? g_dinv[sl]  : 0.f;
            int m = end - e0; if (m > 32) m = 32;
            for (int j = 0; j < m; j++) {
                int   sj  = __shfl_sync(0xffffffffu, sl, j);
                float dsj = __shfl_sync(0xffffffffu, dl, j);
                float4 hs = *((const float4*)(h + (size_t)sj * DF) + lane);
                ax = fmaf(hs.x, dsj, ax);
                ay = fmaf(hs.y, dsj, ay);
                az = fmaf(hs.z, dsj, az);
                aw = fmaf(hs.w, dsj, aw);
            }
        }
        float ox = fmaxf(fmaf(ax, dv, bv.x), 0.f);
        float oy = fmaxf(fmaf(ay, dv, bv.y), 0.f);
        float oz = fmaxf(fmaf(az, dv, bv.z), 0.f);
        float ow = fmaxf(fmaf(aw, dv, bv.w), 0.f);
        *((float4*)(xout + (size_t)v * DF) + lane) = make_float4(ox, oy, oz, ow);
        ls0 += ox; lq0 += ox * ox;
        ls1 += oy; lq1 += oy * oy;
        ls2 += oz; lq2 += oz * oz;
        ls3 += ow; lq3 += ow * ow;
    }
    atomicAdd(&bs[lane * 4 + 0], ls0); atomicAdd(&bq[lane * 4 + 0], lq0);
    atomicAdd(&bs[lane * 4 + 1], ls1); atomicAdd(&bq[lane * 4 + 1], lq1);
    atomicAdd(&bs[lane * 4 + 2], ls2); atomicAdd(&bq[lane * 4 + 2], lq2);
    atomicAdd(&bs[lane * 4 + 3], ls3); atomicAdd(&bq[lane * 4 + 3], lq3);
    __syncthreads();
    if (tid < DF) {
        atomicAdd(&g_bnsum[tid], bs[tid]);
        atomicAdd(&g_bnsq[tid],  bq[tid]);
    }
}

// ------------------- BN affine parameters: a = g*rsqrt(var+eps), c = beta - a*mean -------------------
__global__ void k_bnaff(const float* __restrict__ sum, const float* __restrict__ sq,
                        const float* __restrict__ gamma, const float* __restrict__ beta,
                        float* __restrict__ a, float* __restrict__ c,
                        int D, float invN)
{
    int j = blockIdx.x * blockDim.x + threadIdx.x;
    if (j >= D) return;
    float m   = sum[j] * invN;
    float var = sq[j] * invN - m * m;
    float aj  = gamma[j] * rsqrtf(var + 1e-5f);
    a[j] = aj;
    c[j] = beta[j] - aj * m;
}

// Wmod[k][j] = a[k] * W[k][j]
__global__ void k_wprep(const float* __restrict__ W) {
    int i = blockIdx.x * blockDim.x + threadIdx.x;
    if (i < DF * DF) g_Wmod[i] = g_affa[i >> 7] * W[i];
}
// d[j] = sum_k c[k] * W[k][j]
__global__ void k_dvec(const float* __restrict__ W) {
    int j = threadIdx.x;
    if (j < DF) {
        float s = 0.f;
        for (int k = 0; k < DF; k++) s = fmaf(g_affc[k], W[k * DF + j], s);
        g_dvec[j] = s;
    }
}

// ------------------- global_add_pool (batch is sorted -> run-length accumulation) -------------------
__global__ void k_pool(const float* __restrict__ x, const int* __restrict__ batch) {
    int lane = threadIdx.x & 31;
    int w    = (blockIdx.x * blockDim.x + threadIdx.x) >> 5;
    int nW   = (gridDim.x * blockDim.x) >> 5;
    int C    = (NN + nW - 1) / nW;
    int beg = w * C;
    int end = beg + C; if (end > NN) end = NN;
    if (beg >= end) return;

    float a0 = 0, a1 = 0, a2 = 0, a3 = 0, cntf = 0;
    int cur = batch[beg];
    for (int v = beg; v < end; v++) {
        int g = batch[v];
        if (g != cur) {
            atomicAdd(&g_pool[cur * DF + lane * 4 + 0], a0);
            atomicAdd(&g_pool[cur * DF + lane * 4 + 1], a1);
            atomicAdd(&g_pool[cur * DF + lane * 4 + 2], a2);
            atomicAdd(&g_pool[cur * DF + lane * 4 + 3], a3);
            if (lane == 0) atomicAdd(&g_gcnt[cur], cntf);
            a0 = a1 = a2 = a3 = 0.f; cntf = 0.f; cur = g;
        }
        float4 xv = *((const float4*)(x + (size_t)v * DF) + lane);
        a0 += xv.x; a1 += xv.y; a2 += xv.z; a3 += xv.w; cntf += 1.f;
    }
    atomicAdd(&g_pool[cur * DF + lane * 4 + 0], a0);
    atomicAdd(&g_pool[cur * DF + lane * 4 + 1], a1);
    atomicAdd(&g_pool[cur * DF + lane * 4 + 2], a2);
    atomicAdd(&g_pool[cur * DF + lane * 4 + 3], a3);
    if (lane == 0) atomicAdd(&g_gcnt[cur], cntf);
}

// ------------------- head -------------------
// h0 = relu((a2*pool + c2*cnt) @ Wh0 + bh0), fused BN stats
__global__ void __launch_bounds__(256) k_hg0(const float* __restrict__ Wh0,
                                             const float* __restrict__ bh0) {
    __shared__ float sx[DF];
    int g = blockIdx.x, j = threadIdx.x;
    if (j < DF) sx[j] = g_affa[j] * g_pool[g * DF + j] + g_affc[j] * g_gcnt[g];
    __syncthreads();
    float acc = bh0[j];
#pragma unroll 8
    for (int k = 0; k < DF; k++) acc = fmaf(sx[k], Wh0[k * DH + j], acc);
    float v = fmaxf(acc, 0.f);
    g_h0[g * DH + j] = v;
    atomicAdd(&g_s0[j], v);
    atomicAdd(&g_q0[j], v * v);
}

// h1 = relu((a*h0 + c) @ Wh1 + bh1), fused BN stats
__global__ void __launch_bounds__(256) k_hg1(const float* __restrict__ Wh1,
                                             const float* __restrict__ bh1) {
    __shared__ float sx[DH];
    int g = blockIdx.x, j = threadIdx.x;
    sx[j] = g_ha[j] * g_h0[g * DH + j] + g_hc[j];
    __syncthreads();
    float acc = bh1[j];
#pragma unroll 8
    for (int k = 0; k < DH; k++) acc = fmaf(sx[k], Wh1[k * DH + j], acc);
    float v = fmaxf(acc, 0.f);
    g_h1[g * DH + j] = v;
    atomicAdd(&g_s0[j], v);
    atomicAdd(&g_q0[j], v * v);
}

// out[g] = (a*h1 + c) @ Wout + bout
__global__ void __launch_bounds__(256) k_final(const float* __restrict__ Wout,
                                               const float* __restrict__ bout,
                                               float* __restrict__ out) {
    __shared__ float red[DH];
    int g = blockIdx.x, t = threadIdx.x;
    red[t] = (g_ha[t] * g_h1[g * DH + t] + g_hc[t]) * Wout[t];
    __syncthreads();
    for (int o = DH / 2; o > 0; o >>= 1) {
        if (t < o) red[t] += red[t + o];
        __syncthreads();
    }
    if (t == 0) out[g] = red[0] + bout[0];
}

// ------------------- launch -------------------
extern "C" void kernel_launch(void* const* d_in, const int* in_sizes, int n_in,
                              void* d_out, int out_size) {
    const float* x   = (const float*)d_in[0];
    const int*   ei  = (const int*)d_in[1];
    const int*   bat = (const int*)d_in[2];
    const float* Wc  = (const float*)d_in[3];
    const float* bc  = (const float*)d_in[4];
    const float* gc  = (const float*)d_in[5];
    const float* bec = (const float*)d_in[6];
    const float* Wh0 = (const float*)d_in[7];
    const float* bh0 = (const float*)d_in[8];
    const float* gh0 = (const float*)d_in[9];
    const float* beh0= (const float*)d_in[10];
    const float* Wh1 = (const float*)d_in[11];
    const float* bh1 = (const float*)d_in[12];
    const float* gh1 = (const float*)d_in[13];
    const float* beh1= (const float*)d_in[14];
    const float* Wout= (const float*)d_in[15];
    const float* bout= (const float*)d_in[16];
    float* out = (float*)d_out;

    const int* src = ei;
    const int* dst = ei + NE;

    float *p_x0, *p_x1, *p_h, *p_Wmod, *p_dvec, *p_bnsum, *p_bnsq;
    float *p_affa, *p_affc, *p_pool, *p_gcnt, *p_s0, *p_q0, *p_ha, *p_hc;
    int   *p_cnt;
    cudaGetSymbolAddress((void**)&p_x0,   g_x0);
    cudaGetSymbolAddress((void**)&p_x1,   g_x1);
    cudaGetSymbolAddress((void**)&p_h,    g_h);
    cudaGetSymbolAddress((void**)&p_Wmod, g_Wmod);
    cudaGetSymbolAddress((void**)&p_dvec, g_dvec);
    cudaGetSymbolAddress((void**)&p_bnsum,g_bnsum);
    cudaGetSymbolAddress((void**)&p_bnsq, g_bnsq);
    cudaGetSymbolAddress((void**)&p_affa, g_affa);
    cudaGetSymbolAddress((void**)&p_affc, g_affc);
    cudaGetSymbolAddress((void**)&p_pool, g_pool);
    cudaGetSymbolAddress((void**)&p_gcnt, g_gcnt);
    cudaGetSymbolAddress((void**)&p_s0,   g_s0);
    cudaGetSymbolAddress((void**)&p_q0,   g_q0);
    cudaGetSymbolAddress((void**)&p_ha,   g_ha);
    cudaGetSymbolAddress((void**)&p_hc,   g_hc);
    cudaGetSymbolAddress((void**)&p_cnt,  g_cnt);

    const int T = 256;
    const int gemmBlocks = (NN + 127) / 128;

    // ---- CSR build + degree ----
    k_zero_i<<<(NN + T - 1) / T, T>>>(p_cnt, NN);
    k_hist<<<(NE + T - 1) / T, T>>>(dst);
    k_dinv<<<(NN + T - 1) / T, T>>>();
    k_scanA<<<SB, 256>>>();
    k_scanB<<<1, 512>>>();
    k_scanC<<<SB, 256>>>();
    k_fill<<<(NE + T - 1) / T, T>>>(src, dst);

    // ---- conv layer 0 ----
    k_sgemm<<<gemmBlocks, T>>>(x, Wc, nullptr, p_h, NN);
    k_zero_f<<<1, DF>>>(p_bnsum, DF);
    k_zero_f<<<1, DF>>>(p_bnsq, DF);
    k_agg<<<2048, T>>>(p_h, bc, p_x0);
    k_bnaff<<<1, DF>>>(p_bnsum, p_bnsq, gc, bec, p_affa, p_affc, DF, 1.0f / NN);

    // ---- conv layer 1 (BN0 folded into GEMM) ----
    k_wprep<<<(DF * DF + T - 1) / T, T>>>(Wc + DF * DF);
    k_dvec<<<1, DF>>>(Wc + DF * DF);
    k_sgemm<<<gemmBlocks, T>>>(p_x0, p_Wmod, p_dvec, p_h, NN);
    k_zero_f<<<1, DF>>>(p_bnsum, DF);
    k_zero_f<<<1, DF>>>(p_bnsq, DF);
    k_agg<<<2048, T>>>(p_h, bc + DF, p_x1);
    k_bnaff<<<1, DF>>>(p_bnsum, p_bnsq, gc + DF, bec + DF, p_affa, p_affc, DF, 1.0f / NN);

    // ---- conv layer 2 ----
    k_wprep<<<(DF * DF + T - 1) / T, T>>>(Wc + 2 * DF * DF);
    k_dvec<<<1, DF>>>(Wc + 2 * DF * DF);
    k_sgemm<<<gemmBlocks, T>>>(p_x1, p_Wmod, p_dvec, p_h, NN);
    k_zero_f<<<1, DF>>>(p_bnsum, DF);
    k_zero_f<<<1, DF>>>(p_bnsq, DF);
    k_agg<<<2048, T>>>(p_h, bc + 2 * DF, p_x0);
    k_bnaff<<<1, DF>>>(p_bnsum, p_bnsq, gc + 2 * DF, bec + 2 * DF, p_affa, p_affc, DF, 1.0f / NN);

    // ---- pool (BN2 applied in head gemm0 via g_affa/g_affc) ----
    k_zero_f<<<(NG * DF + T - 1) / T, T>>>(p_pool, NG * DF);
    k_zero_f<<<(NG + T - 1) / T, T>>>(p_gcnt, NG);
    k_pool<<<128, T>>>(p_x0, bat);

    // ---- head ----
    k_zero_f<<<1, DH>>>(p_s0, DH);
    k_zero_f<<<1, DH>>>(p_q0, DH);
    k_hg0<<<NG, DH>>>(Wh0, bh0);
    k_bnaff<<<1, DH>>>(p_s0, p_q0, gh0, beh0, p_ha, p_hc, DH, 1.0f / NG);
    k_zero_f<<<1, DH>>>(p_s0, DH);
    k_zero_f<<<1, DH>>>(p_q0, DH);
    k_hg1<<<NG, DH>>>(Wh1, bh1);
    k_bnaff<<<1, DH>>>(p_s0, p_q0, gh1, beh1, p_ha, p_hc, DH, 1.0f / NG);
    k_final<<<NG, DH>>>(Wout, bout, out);
}